// round 2
// baseline (speedup 1.0000x reference)
#include <cuda_runtime.h>
#include <math.h>

// ---------------- problem constants ----------------
#define CIN_     64
#define HIN      56
#define HOUT     54
#define PIX_B    (HOUT * HOUT)            // 2916 output pixels per image
#define BATCH    8
#define NPIX_TOT (BATCH * CIN_ * HIN * HIN) // 1605632 input pixels total
#define NROWS    (BATCH * PIX_B)          // 23328 GEMM rows
#define COUT_    128
#define NF       9                         // 1 silu + 8 spline bases
#define KKF      81                        // 9 (3x3 taps) * 9 features
#define KKF_PAD  84                        // padded to multiple of 4
#define TM       32                        // rows per CTA (23328 % 32 == 0 -> 729 CTAs)
#define IN_FEAT  576                       // CIN_*9

#define SMEM_FLOATS (KKF_PAD * COUT_ + TM * KKF_PAD)   // 10752 + 2688 = 13440
#define SMEM_BYTES  (SMEM_FLOATS * 4)                  // 53760

// ---------------- scratch (static device memory; no allocs) ----------------
__device__ float g_F[NF * NPIX_TOT];          // ~57.8 MB: per-pixel features, planar [f][pixel]
__device__ float g_W2[CIN_ * KKF * COUT_];    // ~2.65 MB: folded weights [(c*9+kk)*9+f][o]

// ---------------- stage 1: per-pixel features (silu + 8 cubic B-spline bases) ----------------
// knots t_j = -2.2 + 0.4*j, j=0..11; degree-3 cardinal B-splines.
// For x in interval s (local coord u), basis f = s - r evaluates piece_r(u), r=0..3.
__global__ __launch_bounds__(256) void kan_feat(const float* __restrict__ x) {
    int i = blockIdx.x * blockDim.x + threadIdx.x;
    if (i >= NPIX_TOT) return;
    float v = x[i];

    // silu
    float s = v / (1.0f + expf(-v));

    // interval + local coordinate
    float un = (v + 2.2f) * 2.5f;        // (v - t0)/h
    float sf = floorf(un);
    int   si = (int)sf;
    float u  = un - sf;
    float u2 = u * u, u3 = u2 * u;
    const float c6 = 1.0f / 6.0f;
    float p0 = u3 * c6;                                   // r=0
    float p1 = (1.0f + 3.0f*u + 3.0f*u2 - 3.0f*u3) * c6;  // r=1
    float p2 = (4.0f - 6.0f*u2 + 3.0f*u3) * c6;           // r=2
    float p3 = (1.0f - 3.0f*u + 3.0f*u2 - u3) * c6;       // r=3
    bool inr = (si >= 0) && (si <= 10);

    g_F[i] = s;   // f = 0 plane
#pragma unroll
    for (int f = 0; f < 8; ++f) {
        int r = si - f;   // piece index for basis f
        float b = 0.0f;
        if (inr) {
            if      (r == 0) b = p0;
            else if (r == 1) b = p1;
            else if (r == 2) b = p2;
            else if (r == 3) b = p3;
        }
        g_F[(f + 1) * NPIX_TOT + i] = b;
    }
}

// ---------------- stage 2: fold weights: W2[(c*9+kk)*9+f][o] ----------------
__global__ __launch_bounds__(256) void kan_wprep(const float* __restrict__ bw,
                                                 const float* __restrict__ sw,
                                                 const float* __restrict__ sc) {
    int idx = blockIdx.x * blockDim.x + threadIdx.x;   // over COUT_*IN_FEAT
    if (idx >= COUT_ * IN_FEAT) return;
    int o = idx & (COUT_ - 1);
    int i = idx >> 7;                                  // 0..575  (= c*9 + kk)
    float scale = sc[o * IN_FEAT + i];
    g_W2[(i * 9 + 0) * COUT_ + o] = bw[o * IN_FEAT + i];
#pragma unroll
    for (int g = 0; g < 8; ++g)
        g_W2[(i * 9 + 1 + g) * COUT_ + o] = sw[(o * IN_FEAT + i) * 8 + g] * scale;
}

// ---------------- stage 3: fused conv-GEMM ----------------
// Each CTA: 32 output rows x 128 outputs. Loop over 64 input channels; per channel
// stage weights (81x128) and gathered activations (32x81, 3x3 taps x 9 feats) in smem.
// Thread: 2 outputs (o, o+64) x 8 rows. Inner: float4 broadcast act load -> 8 FMAs.
__global__ __launch_bounds__(256) void kan_gemm(float* __restrict__ out) {
    extern __shared__ float sh[];
    float* wsh = sh;                          // [KKF_PAD][COUT_]
    float* act = sh + KKF_PAD * COUT_;        // [TM][KKF_PAD]
    __shared__ int rowoff[TM];
    __shared__ int outoff[TM];
    __shared__ int colmap[KKF];               // col -> f*NPIX_TOT + ky*HIN + kx

    const int tid = threadIdx.x;
    const int o0  = tid & 63;
    const int o1  = o0 + 64;
    const int rg  = tid >> 6;                 // 0..3 -> rows rg*8 .. rg*8+7

    if (tid < TM) {
        int n   = blockIdx.x * TM + tid;
        int b   = n / PIX_B;
        int rem = n - b * PIX_B;
        int y   = rem / HOUT;
        int xx  = rem - y * HOUT;
        rowoff[tid] = b * (CIN_ * HIN * HIN) + y * HIN + xx;   // pixel offset (c added later)
        outoff[tid] = b * (COUT_ * PIX_B) + rem;
    }
    if (tid >= 64 && tid < 64 + KKF) {        // warps 2-4: build column map
        int col = tid - 64;
        int kk  = col / 9;
        int f   = col - kk * 9;
        int ky  = kk / 3;
        int kx  = kk - ky * 3;
        colmap[col] = f * NPIX_TOT + ky * HIN + kx;
    }
    // zero pads (cols 81..83 of both buffers) once
    for (int i = tid; i < 3 * COUT_; i += 256) wsh[KKF * COUT_ + i] = 0.0f;
    for (int i = tid; i < TM * 3;   i += 256) act[(i / 3) * KKF_PAD + KKF + (i % 3)] = 0.0f;

    float acc0[8], acc1[8];
#pragma unroll
    for (int rr = 0; rr < 8; ++rr) { acc0[rr] = 0.0f; acc1[rr] = 0.0f; }

    for (int c = 0; c < CIN_; ++c) {
        __syncthreads();
        // ---- load weights for this channel (contiguous, float4) ----
        {
            const float4* src = (const float4*)(g_W2 + c * KKF * COUT_);
            float4*       dst = (float4*)wsh;
            for (int i = tid; i < (KKF * COUT_) / 4; i += 256) dst[i] = src[i];
        }
        // ---- gather activations: act[r][col] = F[colmap[col] + pix(r) + c*3136] ----
        {
            const float* Fc = g_F + c * (HIN * HIN);
            for (int i = tid; i < KKF * TM; i += 256) {
                int r   = i & (TM - 1);
                int col = i >> 5;              // 0..80
                act[r * KKF_PAD + col] = Fc[colmap[col] + rowoff[r]];
            }
        }
        __syncthreads();
        // ---- compute ----
        const float* abase = act + rg * 8 * KKF_PAD;
#pragma unroll 3
        for (int kb = 0; kb < KKF_PAD; kb += 4) {
            float w00 = wsh[(kb + 0) * COUT_ + o0];
            float w01 = wsh[(kb + 1) * COUT_ + o0];
            float w02 = wsh[(kb + 2) * COUT_ + o0];
            float w03 = wsh[(kb + 3) * COUT_ + o0];
            float w10 = wsh[(kb + 0) * COUT_ + o1];
            float w11 = wsh[(kb + 1) * COUT_ + o1];
            float w12 = wsh[(kb + 2) * COUT_ + o1];
            float w13 = wsh[(kb + 3) * COUT_ + o1];
#pragma unroll
            for (int rr = 0; rr < 8; ++rr) {
                float4 a = *(const float4*)(abase + rr * KKF_PAD + kb);
                acc0[rr] = fmaf(a.x, w00, acc0[rr]);
                acc0[rr] = fmaf(a.y, w01, acc0[rr]);
                acc0[rr] = fmaf(a.z, w02, acc0[rr]);
                acc0[rr] = fmaf(a.w, w03, acc0[rr]);
                acc1[rr] = fmaf(a.x, w10, acc1[rr]);
                acc1[rr] = fmaf(a.y, w11, acc1[rr]);
                acc1[rr] = fmaf(a.z, w12, acc1[rr]);
                acc1[rr] = fmaf(a.w, w13, acc1[rr]);
            }
        }
    }

    // ---- transpose through smem for coalesced output stores ----
    __syncthreads();
    float* sout = sh;                         // [COUT_][TM+1]
#pragma unroll
    for (int rr = 0; rr < 8; ++rr) {
        int r = rg * 8 + rr;
        sout[o0 * (TM + 1) + r] = acc0[rr];
        sout[o1 * (TM + 1) + r] = acc1[rr];
    }
    __syncthreads();
    for (int i = tid; i < COUT_ * TM; i += 256) {
        int o = i >> 5;
        int r = i & (TM - 1);
        out[outoff[r] + o * PIX_B] = sout[o * (TM + 1) + r];
    }
}

// ---------------- launch ----------------
extern "C" void kernel_launch(void* const* d_in, const int* in_sizes, int n_in,
                              void* d_out, int out_size) {
    const float* x  = (const float*)d_in[0];   // (8,64,56,56)
    const float* bw = (const float*)d_in[1];   // (128,576)
    const float* sw = (const float*)d_in[2];   // (128,576,8)
    const float* sc = (const float*)d_in[3];   // (128,576)
    float* out = (float*)d_out;                // (8,128,54,54)

    (void)in_sizes; (void)n_in; (void)out_size;

    cudaFuncSetAttribute(kan_gemm, cudaFuncAttributeMaxDynamicSharedMemorySize, SMEM_BYTES);

    kan_feat<<<(NPIX_TOT + 255) / 256, 256>>>(x);
    kan_wprep<<<(COUT_ * IN_FEAT + 255) / 256, 256>>>(bw, sw, sc);
    kan_gemm<<<NROWS / TM, 256, SMEM_BYTES>>>(out);
}

// round 4
// speedup vs baseline: 3.0372x; 3.0372x over previous
#include <cuda_runtime.h>
#include <cstdint>
#include <math.h>

// ================= problem constants =================
#define CIN_     64
#define HIN      56
#define HOUT     54
#define PIX_B    (HOUT * HOUT)              // 2916
#define BATCH    8
#define NPIX_TOT (BATCH * CIN_ * HIN * HIN) // 1605632
#define NROWS    (BATCH * PIX_B)            // 23328
#define COUT_    128
#define IN_FEAT  576
#define KTOT     5184                        // 64 ch * 81
#define KC       32                          // K per stage
#define NSTG     (KTOT / KC)                 // 162
#define MTILE    96
#define CTAS     (NROWS / MTILE)             // 243 exact

// smem geometry (floats)
#define SA       36                          // padded A row stride
#define SB       36                          // padded B row stride
#define A_FLT    (MTILE * SA)                // 3456
#define B_FLT    (COUT_ * SB)                // 4608
#define STAGE_FLT (A_FLT + B_FLT)            // 8064
#define STAGE_BYTES (STAGE_FLT * 4)          // 32256
#define A_BYTES  (A_FLT * 4)                 // 13824
#define NBUF     3
#define DYN_SMEM (NBUF * STAGE_BYTES)        // 96768
#define SO       132                         // epilogue sout stride

// ================= device scratch (static; no allocs) =================
__device__ float g_F[9 * NPIX_TOT];          // per-pixel features (tf32-rounded)
__device__ float g_W2[COUT_ * KTOT];         // folded weights [o][k] (tf32-rounded)
__device__ int   g_kmap[KTOT];               // k -> f*NPIX + c*3136 + ky*56 + kx

// ================= helpers =================
__device__ __forceinline__ uint32_t smem_u32(const void* p) {
    uint32_t a;
    asm("{ .reg .u64 t; cvta.to.shared.u64 t, %1; cvt.u32.u64 %0, t; }" : "=r"(a) : "l"(p));
    return a;
}
__device__ __forceinline__ float rna_tf32(float f) {
    uint32_t u; asm("cvt.rna.tf32.f32 %0, %1;" : "=r"(u) : "f"(f));
    return __uint_as_float(u);
}
#define CP4(dst, src)  asm volatile("cp.async.ca.shared.global [%0], [%1], 4;"  :: "r"(dst), "l"(src) : "memory")
#define CP16(dst, src) asm volatile("cp.async.cg.shared.global [%0], [%1], 16;" :: "r"(dst), "l"(src) : "memory")
#define CPCOMMIT()     asm volatile("cp.async.commit_group;" ::: "memory")
#define CPWAIT(n)      asm volatile("cp.async.wait_group %0;" :: "n"(n) : "memory")

__device__ __forceinline__ void mma8(float* c, const uint32_t* a, const uint32_t* b) {
    asm volatile("mma.sync.aligned.m16n8k8.row.col.f32.tf32.tf32.f32 "
        "{%0,%1,%2,%3}, {%4,%5,%6,%7}, {%8,%9}, {%0,%1,%2,%3};"
        : "+f"(c[0]), "+f"(c[1]), "+f"(c[2]), "+f"(c[3])
        : "r"(a[0]), "r"(a[1]), "r"(a[2]), "r"(a[3]), "r"(b[0]), "r"(b[1]));
}

// ================= stage 1: per-pixel features (tf32-rounded) =================
__global__ __launch_bounds__(256) void kan_feat(const float* __restrict__ x) {
    int i = blockIdx.x * blockDim.x + threadIdx.x;
    if (i >= NPIX_TOT) return;
    float v = x[i];
    float s = v / (1.0f + expf(-v));
    float un = (v + 2.2f) * 2.5f;
    float sf = floorf(un);
    int   si = (int)sf;
    float u  = un - sf;
    float u2 = u * u, u3 = u2 * u;
    const float c6 = 1.0f / 6.0f;
    float p0 = u3 * c6;
    float p1 = (1.0f + 3.0f*u + 3.0f*u2 - 3.0f*u3) * c6;
    float p2 = (4.0f - 6.0f*u2 + 3.0f*u3) * c6;
    float p3 = (1.0f - 3.0f*u + 3.0f*u2 - u3) * c6;
    bool inr = (si >= 0) && (si <= 10);
    g_F[i] = rna_tf32(s);
#pragma unroll
    for (int f = 0; f < 8; ++f) {
        int r = si - f;
        float b = 0.0f;
        if (inr) {
            if      (r == 0) b = p0;
            else if (r == 1) b = p1;
            else if (r == 2) b = p2;
            else if (r == 3) b = p3;
        }
        g_F[(f + 1) * NPIX_TOT + i] = rna_tf32(b);
    }
}

// ================= stage 2: fold weights + build k-map =================
__global__ __launch_bounds__(256) void kan_wprep(const float* __restrict__ bw,
                                                 const float* __restrict__ sw,
                                                 const float* __restrict__ sc) {
    int idx = blockIdx.x * blockDim.x + threadIdx.x;
    if (idx < KTOT) {
        int c   = idx / 81;
        int rem = idx - c * 81;
        int kk  = rem / 9;
        int f   = rem - kk * 9;
        int ky  = kk / 3;
        int kx  = kk - ky * 3;
        g_kmap[idx] = f * NPIX_TOT + c * (HIN * HIN) + ky * HIN + kx;
    }
    if (idx >= COUT_ * IN_FEAT) return;
    int o = idx & (COUT_ - 1);
    int i = idx >> 7;                        // 0..575 (= c*9+kk)
    float scale = sc[o * IN_FEAT + i];
    float* dst = g_W2 + o * KTOT + i * 9;
    dst[0] = rna_tf32(bw[o * IN_FEAT + i]);
#pragma unroll
    for (int g = 0; g < 8; ++g)
        dst[1 + g] = rna_tf32(sw[(o * IN_FEAT + i) * 8 + g] * scale);
}

// ================= stage 3: tf32 mma.sync GEMM (portable HMMA path) =================
// CTA: 96 rows x 128 outs, K pipelined in 32-chunks, 3-stage cp.async ring.
// 8 warps as 2(m) x 4(n): warp tile 48x32; m16n8k8 frags: 3 x 4 per k8 step.
__global__ __launch_bounds__(256, 2) void kan_mma(float* __restrict__ out) {
    extern __shared__ uint32_t smu[];
    __shared__ int sh_ooff[MTILE];

    const int tid  = threadIdx.x;
    const int wid  = tid >> 5;
    const int lane = tid & 31;

    // ---- producer constants (A gather) ----
    const int r0 = tid & 7;          // row within 8-group
    const int kj = tid >> 3;         // 0..31: k within chunk
    const int base_n = blockIdx.x * MTILE;
    int ro[12];
#pragma unroll
    for (int i = 0; i < 12; ++i) {
        int n   = base_n + r0 + 8 * i;
        int b   = n / PIX_B;
        int rem = n - b * PIX_B;
        int y   = rem / HOUT;
        int xx  = rem - y * HOUT;
        ro[i] = b * (CIN_ * HIN * HIN) + y * HIN + xx;
    }
    if (tid < MTILE) {
        int n   = base_n + tid;
        int b   = n / PIX_B;
        int rem = n - b * PIX_B;
        sh_ooff[tid] = b * (COUT_ * PIX_B) + rem;
    }

    const uint32_t smb = smem_u32(smu);
    const int bo = tid >> 3;         // B: output row group
    const int bg = tid & 7;          // B: 16B granule

    // ---- compute constants ----
    const int wm = wid & 1;          // 0-1 -> rows wm*48
    const int wn = wid >> 1;         // 0-3 -> cols wn*32
    const int g  = lane >> 2;
    const int t  = lane & 3;

    float acc[3][4][4];
#pragma unroll
    for (int mt = 0; mt < 3; ++mt)
#pragma unroll
        for (int nt = 0; nt < 4; ++nt)
#pragma unroll
            for (int e = 0; e < 4; ++e) acc[mt][nt][e] = 0.0f;

    // ---- stage loaders ----
    auto loadA = [&](int s, int buf) {
        const int km = __ldg(&g_kmap[s * KC + kj]);
        const float* src = g_F + km;
        uint32_t dst = smb + buf * STAGE_BYTES + (r0 * SA + kj) * 4;
#pragma unroll
        for (int i = 0; i < 12; ++i)
            CP4(dst + i * (8 * SA * 4), src + ro[i]);
    };
    auto loadB = [&](int s, int buf) {
        uint32_t dst = smb + buf * STAGE_BYTES + A_BYTES + (bo * SB + bg * 4) * 4;
        const float* src = g_W2 + bo * KTOT + s * KC + bg * 4;
#pragma unroll
        for (int it = 0; it < 4; ++it)
            CP16(dst + it * (32 * SB * 4), src + it * (32 * KTOT));
    };

    // ---- prologue: stages 0,1 ----
    loadA(0, 0); loadB(0, 0); CPCOMMIT();
    loadA(1, 1); loadB(1, 1); CPCOMMIT();

    // ---- mainloop ----
    for (int s = 0; s < NSTG; ++s) {
        const int buf = s % NBUF;
        CPWAIT(1);
        __syncthreads();
        if (s + 2 < NSTG) {
            int nb = (s + 2) % NBUF;
            loadA(s + 2, nb);
            loadB(s + 2, nb);
        }
        CPCOMMIT();

        const uint32_t* As = smu + buf * STAGE_FLT;
        const uint32_t* Bs = As + A_FLT;
#pragma unroll
        for (int ks = 0; ks < 4; ++ks) {
            const int k0 = ks * 8;
            uint32_t a[3][4], b[4][2];
#pragma unroll
            for (int mt = 0; mt < 3; ++mt) {
                int r = wm * 48 + mt * 16 + g;
                a[mt][0] = As[r * SA + k0 + t];
                a[mt][1] = As[(r + 8) * SA + k0 + t];
                a[mt][2] = As[r * SA + k0 + t + 4];
                a[mt][3] = As[(r + 8) * SA + k0 + t + 4];
            }
#pragma unroll
            for (int nt = 0; nt < 4; ++nt) {
                int n = wn * 32 + nt * 8 + g;
                b[nt][0] = Bs[n * SB + k0 + t];
                b[nt][1] = Bs[n * SB + k0 + t + 4];
            }
#pragma unroll
            for (int mt = 0; mt < 3; ++mt)
#pragma unroll
                for (int nt = 0; nt < 4; ++nt)
                    mma8(acc[mt][nt], a[mt], b[nt]);
        }
    }

    CPWAIT(0);
    __syncthreads();

    // ---- epilogue: regs -> smem transpose -> coalesced strided stores ----
    float* sout = (float*)smu;                 // 96 x SO <= dyn smem
    const int t2 = t * 2;
#pragma unroll
    for (int mt = 0; mt < 3; ++mt) {
        int r = wm * 48 + mt * 16 + g;
#pragma unroll
        for (int nt = 0; nt < 4; ++nt) {
            int cc = wn * 32 + nt * 8 + t2;
            sout[r * SO + cc]           = acc[mt][nt][0];
            sout[r * SO + cc + 1]       = acc[mt][nt][1];
            sout[(r + 8) * SO + cc]     = acc[mt][nt][2];
            sout[(r + 8) * SO + cc + 1] = acc[mt][nt][3];
        }
    }
    __syncthreads();
#pragma unroll
    for (int o = wid; o < COUT_; o += 8) {
#pragma unroll
        for (int rg = 0; rg < 3; ++rg) {
            int r = rg * 32 + lane;
            out[sh_ooff[r] + o * PIX_B] = sout[r * SO + o];
        }
    }
}

// ================= launch =================
extern "C" void kernel_launch(void* const* d_in, const int* in_sizes, int n_in,
                              void* d_out, int out_size) {
    const float* x  = (const float*)d_in[0];   // (8,64,56,56)
    const float* bw = (const float*)d_in[1];   // (128,576)
    const float* sw = (const float*)d_in[2];   // (128,576,8)
    const float* sc = (const float*)d_in[3];   // (128,576)
    float* out = (float*)d_out;                // (8,128,54,54)
    (void)in_sizes; (void)n_in; (void)out_size;

    cudaFuncSetAttribute(kan_mma, cudaFuncAttributeMaxDynamicSharedMemorySize, DYN_SMEM);

    kan_feat<<<(NPIX_TOT + 255) / 256, 256>>>(x);
    kan_wprep<<<(COUT_ * IN_FEAT + 255) / 256, 256>>>(bw, sw, sc);
    kan_mma<<<CTAS, 256, DYN_SMEM>>>(out);
}

// round 5
// speedup vs baseline: 4.4037x; 1.4499x over previous
#include <cuda_runtime.h>
#include <cuda_fp16.h>
#include <cstdint>
#include <math.h>

// ================= problem constants =================
#define CIN_     64
#define HIN      56
#define HOUT     54
#define PIX_B    (HOUT * HOUT)              // 2916
#define BATCH    8
#define NPIX_TOT (BATCH * CIN_ * HIN * HIN) // 1605632
#define NROWS    (BATCH * PIX_B)            // 23328
#define COUT_    128
#define IN_FEAT  576
#define KTOT     5184                        // 64 ch * 81
#define KC       64                          // K per stage
#define NSTG     (KTOT / KC)                 // 81
#define MTILE    96
#define CTAS     (NROWS / MTILE)             // 243 exact

// smem geometry (halves)
#define SAH      104                         // A^T row stride (13*16B -> ldmatrix conflict-free)
#define SBH      72                          // B row stride (9*16B)
#define A_STAGE_BYTES (KC * SAH * 2)         // 13312
#define B_STAGE_BYTES (COUT_ * SBH * 2)      // 18432
#define STAGE_BYTES   (A_STAGE_BYTES + B_STAGE_BYTES)  // 31744
#define NBUF     3
#define DYN_SMEM (NBUF * STAGE_BYTES + 256)  // 95488 (+align slack)
#define SO       132                         // epilogue sout stride (floats)

// ================= device scratch (static; no allocs) =================
__device__ __half g_Fh[9 * NPIX_TOT];        // ~29MB per-pixel features, planar [f][pixel]
__device__ __half g_W2h[COUT_ * KTOT];       // folded weights [o][k]
__device__ int    g_kmap[KTOT];              // k -> f*NPIX + c*3136 + ky*56 + kx

// ================= helpers =================
__device__ __forceinline__ uint32_t smem_u32(const void* p) {
    uint32_t a;
    asm("{ .reg .u64 t; cvta.to.shared.u64 t, %1; cvt.u32.u64 %0, t; }" : "=r"(a) : "l"(p));
    return a;
}
#define CP16(dst, src) asm volatile("cp.async.cg.shared.global [%0], [%1], 16;" :: "r"(dst), "l"(src) : "memory")
#define CPCOMMIT()     asm volatile("cp.async.commit_group;" ::: "memory")
#define CPWAIT(n)      asm volatile("cp.async.wait_group %0;" :: "n"(n) : "memory")

__device__ __forceinline__ void ldsm4(uint32_t* r, uint32_t a) {
    asm volatile("ldmatrix.sync.aligned.m8n8.x4.shared.b16 {%0,%1,%2,%3}, [%4];"
        : "=r"(r[0]), "=r"(r[1]), "=r"(r[2]), "=r"(r[3]) : "r"(a));
}
__device__ __forceinline__ void ldsm4t(uint32_t* r, uint32_t a) {
    asm volatile("ldmatrix.sync.aligned.m8n8.x4.trans.shared.b16 {%0,%1,%2,%3}, [%4];"
        : "=r"(r[0]), "=r"(r[1]), "=r"(r[2]), "=r"(r[3]) : "r"(a));
}
__device__ __forceinline__ void mma16(float* c, const uint32_t* a, const uint32_t* b) {
    asm volatile("mma.sync.aligned.m16n8k16.row.col.f32.f16.f16.f32 "
        "{%0,%1,%2,%3}, {%4,%5,%6,%7}, {%8,%9}, {%0,%1,%2,%3};"
        : "+f"(c[0]), "+f"(c[1]), "+f"(c[2]), "+f"(c[3])
        : "r"(a[0]), "r"(a[1]), "r"(a[2]), "r"(a[3]), "r"(b[0]), "r"(b[1]));
}

// ================= stage 1: per-pixel features -> fp16 =================
__global__ __launch_bounds__(256) void kan_feat(const float* __restrict__ x) {
    int i = blockIdx.x * blockDim.x + threadIdx.x;
    if (i >= NPIX_TOT) return;
    float v = x[i];
    float s = v / (1.0f + expf(-v));
    float un = (v + 2.2f) * 2.5f;
    float sf = floorf(un);
    int   si = (int)sf;
    float u  = un - sf;
    float u2 = u * u, u3 = u2 * u;
    const float c6 = 1.0f / 6.0f;
    float p0 = u3 * c6;
    float p1 = (1.0f + 3.0f*u + 3.0f*u2 - 3.0f*u3) * c6;
    float p2 = (4.0f - 6.0f*u2 + 3.0f*u3) * c6;
    float p3 = (1.0f - 3.0f*u + 3.0f*u2 - u3) * c6;
    bool inr = (si >= 0) && (si <= 10);
    g_Fh[i] = __float2half_rn(s);
#pragma unroll
    for (int f = 0; f < 8; ++f) {
        int r = si - f;
        float b = 0.0f;
        if (inr) {
            if      (r == 0) b = p0;
            else if (r == 1) b = p1;
            else if (r == 2) b = p2;
            else if (r == 3) b = p3;
        }
        g_Fh[(f + 1) * NPIX_TOT + i] = __float2half_rn(b);
    }
}

// ================= stage 2: fold weights (fp16) + k-map =================
__global__ __launch_bounds__(256) void kan_wprep(const float* __restrict__ bw,
                                                 const float* __restrict__ sw,
                                                 const float* __restrict__ sc) {
    int idx = blockIdx.x * blockDim.x + threadIdx.x;
    if (idx < KTOT) {
        int c   = idx / 81;
        int rem = idx - c * 81;
        int kk  = rem / 9;
        int f   = rem - kk * 9;
        int ky  = kk / 3;
        int kx  = kk - ky * 3;
        g_kmap[idx] = f * NPIX_TOT + c * (HIN * HIN) + ky * HIN + kx;
    }
    if (idx >= COUT_ * IN_FEAT) return;
    int o = idx & (COUT_ - 1);
    int i = idx >> 7;                        // 0..575 (= c*9+kk)
    float scale = sc[o * IN_FEAT + i];
    __half* dst = g_W2h + o * KTOT + i * 9;
    dst[0] = __float2half_rn(bw[o * IN_FEAT + i]);
#pragma unroll
    for (int g = 0; g < 8; ++g)
        dst[1 + g] = __float2half_rn(sw[(o * IN_FEAT + i) * 8 + g] * scale);
}

// ================= stage 3: fp16 mma.sync GEMM with ldmatrix =================
// CTA 96x128, K in 64-chunks, 3-buffer ring.
// A^T in smem [k][m] (stride 104 halves) via LDG.U16 gather -> regs -> STS;
// B [n][k] (stride 72 halves) via 16B cp.async. 8 warps = 2(m) x 4(n): warp 48x32.
__global__ __launch_bounds__(256, 2) void kan_mma(float* __restrict__ out) {
    extern __shared__ char dsm_raw[];
    __shared__ int sh_ooff[MTILE];

    const uint32_t sb0 = smem_u32(dsm_raw);
    const uint32_t smb = (sb0 + 255) & ~255u;
    char* const dsm = dsm_raw + (smb - sb0);

    const int tid  = threadIdx.x;
    const int wid  = tid >> 5;
    const int lane = tid & 31;

    // ---- producer constants ----
    const int m0 = tid & 7;          // row in 8-group
    const int k1 = tid >> 3;         // 0..31 (second k = k1+32)
    const int base_n = blockIdx.x * MTILE;
    int ro[12];
#pragma unroll
    for (int i = 0; i < 12; ++i) {
        int n   = base_n + m0 + 8 * i;
        int b   = n / PIX_B;
        int rem = n - b * PIX_B;
        int y   = rem / HOUT;
        int xx  = rem - y * HOUT;
        ro[i] = b * (CIN_ * HIN * HIN) + y * HIN + xx;
    }
    if (tid < MTILE) {
        int n   = base_n + tid;
        int b   = n / PIX_B;
        int rem = n - b * PIX_B;
        sh_ooff[tid] = b * (COUT_ * PIX_B) + rem;
    }

    // ---- compute constants ----
    const int wm = wid & 1;          // rows wm*48
    const int wn = wid >> 1;         // cols wn*32
    // ldmatrix lane offsets
    const uint32_t a_lane = (uint32_t)(((lane & 7) + ((lane >> 4) << 3)) * SAH
                                       + (((lane >> 3) & 1) << 3)) * 2;
    const uint32_t b_lane = (uint32_t)(((lane & 7) + ((lane >> 4) << 3)) * SBH
                                       + (((lane >> 3) & 1) << 3)) * 2;

    float acc[3][4][4];
#pragma unroll
    for (int mt = 0; mt < 3; ++mt)
#pragma unroll
        for (int nt = 0; nt < 4; ++nt)
#pragma unroll
            for (int e = 0; e < 4; ++e) acc[mt][nt][e] = 0.0f;

    __half av[24];

    auto loadA_regs = [&](int s) {
        const int kma = __ldg(g_kmap + s * KC + k1);
        const int kmb = __ldg(g_kmap + s * KC + k1 + 32);
#pragma unroll
        for (int j = 0; j < 12; ++j) {
            av[j]      = g_Fh[kma + ro[j]];
            av[12 + j] = g_Fh[kmb + ro[j]];
        }
    };
    auto stsA = [&](int buf) {
        __half* Ah = (__half*)(dsm + buf * STAGE_BYTES);
#pragma unroll
        for (int j = 0; j < 12; ++j) {
            Ah[k1 * SAH + m0 + 8 * j]        = av[j];
            Ah[(k1 + 32) * SAH + m0 + 8 * j] = av[12 + j];
        }
    };
    auto loadB = [&](int s, int buf) {
        const int n = tid >> 1;
        const __half* src = g_W2h + n * KTOT + s * KC + (tid & 1) * 32;
        uint32_t d = smb + buf * STAGE_BYTES + A_STAGE_BYTES
                   + (uint32_t)(n * SBH + (tid & 1) * 32) * 2;
#pragma unroll
        for (int i = 0; i < 4; ++i)
            CP16(d + i * 16, src + i * 8);
    };

    // ---- prologue: stages 0,1 ----
    loadA_regs(0); stsA(0); loadB(0, 0); CPCOMMIT();
    loadA_regs(1); stsA(1); loadB(1, 1); CPCOMMIT();

    // ---- mainloop ----
    for (int s = 0; s < NSTG; ++s) {
        const int buf = s % NBUF;
        CPWAIT(1);
        __syncthreads();

        if (s + 2 < NSTG) loadA_regs(s + 2);

        const uint32_t Ab = smb + buf * STAGE_BYTES;
        const uint32_t Bb = Ab + A_STAGE_BYTES;
#pragma unroll
        for (int ks = 0; ks < 4; ++ks) {
            const int k0 = ks * 16;
            uint32_t a[3][4], b[2][4];
#pragma unroll
            for (int mt = 0; mt < 3; ++mt)
                ldsm4t(a[mt], Ab + a_lane
                       + (uint32_t)(k0 * SAH + wm * 48 + mt * 16) * 2);
#pragma unroll
            for (int p = 0; p < 2; ++p)
                ldsm4(b[p], Bb + b_lane
                      + (uint32_t)((wn * 32 + p * 16) * SBH + k0) * 2);
#pragma unroll
            for (int mt = 0; mt < 3; ++mt)
#pragma unroll
                for (int nt = 0; nt < 4; ++nt)
                    mma16(acc[mt][nt], a[mt], &b[nt >> 1][(nt & 1) * 2]);
        }

        if (s + 2 < NSTG) {
            int nb = (s + 2) % NBUF;
            stsA(nb);
            loadB(s + 2, nb);
        }
        CPCOMMIT();
    }

    CPWAIT(0);
    __syncthreads();

    // ---- epilogue: regs -> smem transpose -> coalesced strided stores ----
    float* sout = (float*)dsm;                 // 96 x SO floats
    const int g  = lane >> 2;
    const int t2 = (lane & 3) * 2;
#pragma unroll
    for (int mt = 0; mt < 3; ++mt) {
        int r = wm * 48 + mt * 16 + g;
#pragma unroll
        for (int nt = 0; nt < 4; ++nt) {
            int cc = wn * 32 + nt * 8 + t2;
            sout[r * SO + cc]           = acc[mt][nt][0];
            sout[r * SO + cc + 1]       = acc[mt][nt][1];
            sout[(r + 8) * SO + cc]     = acc[mt][nt][2];
            sout[(r + 8) * SO + cc + 1] = acc[mt][nt][3];
        }
    }
    __syncthreads();
#pragma unroll
    for (int o = wid; o < COUT_; o += 8) {
#pragma unroll
        for (int rg = 0; rg < 3; ++rg) {
            int r = rg * 32 + lane;
            out[sh_ooff[r] + o * PIX_B] = sout[r * SO + o];
        }
    }
}

// ================= launch =================
extern "C" void kernel_launch(void* const* d_in, const int* in_sizes, int n_in,
                              void* d_out, int out_size) {
    const float* x  = (const float*)d_in[0];   // (8,64,56,56)
    const float* bw = (const float*)d_in[1];   // (128,576)
    const float* sw = (const float*)d_in[2];   // (128,576,8)
    const float* sc = (const float*)d_in[3];   // (128,576)
    float* out = (float*)d_out;                // (8,128,54,54)
    (void)in_sizes; (void)n_in; (void)out_size;

    cudaFuncSetAttribute(kan_mma, cudaFuncAttributeMaxDynamicSharedMemorySize, DYN_SMEM);

    kan_feat<<<(NPIX_TOT + 255) / 256, 256>>>(x);
    kan_wprep<<<(COUT_ * IN_FEAT + 255) / 256, 256>>>(bw, sw, sc);
    kan_mma<<<CTAS, 256, DYN_SMEM>>>(out);
}

// round 6
// speedup vs baseline: 4.7203x; 1.0719x over previous
#include <cuda_runtime.h>
#include <cuda_fp16.h>
#include <cstdint>
#include <math.h>

// ================= problem constants =================
#define CIN_     64
#define HIN      56
#define HOUT     54
#define PIX_B    (HOUT * HOUT)              // 2916
#define BATCH    8
#define NPIX_TOT (BATCH * CIN_ * HIN * HIN) // 1605632
#define NROWS    (BATCH * PIX_B)            // 23328
#define COUT_    128
#define IN_FEAT  576
#define KTOT     5184                        // 64 ch * 81
#define KC       64                          // K per stage
#define NSTG     (KTOT / KC)                 // 81
#define MTILE    96
#define CTAS     (NROWS / MTILE)             // 243 exact

// smem geometry (halves)
#define SAH      104                         // A^T row stride (13*16B -> ldmatrix conflict-free)
#define SBH      72                          // B row stride (9*16B)
#define A_STAGE_BYTES (KC * SAH * 2)         // 13312
#define B_STAGE_BYTES (COUT_ * SBH * 2)      // 18432
#define STAGE_BYTES   (A_STAGE_BYTES + B_STAGE_BYTES)  // 31744
#define NBUF     3
#define DYN_SMEM (NBUF * STAGE_BYTES + 256)  // 95488 (+align slack)
#define SO       132                         // epilogue sout stride (floats)

// ================= device scratch (static; no allocs) =================
__device__ __half g_Fh[9 * NPIX_TOT];        // ~29MB per-pixel features, planar [f][pixel]
__device__ __half g_W2h[COUT_ * KTOT];       // folded weights [o][k]
__device__ int    g_kmap[KTOT];              // k -> f*NPIX + c*3136 + ky*56 + kx

// ================= helpers =================
__device__ __forceinline__ uint32_t smem_u32(const void* p) {
    uint32_t a;
    asm("{ .reg .u64 t; cvta.to.shared.u64 t, %1; cvt.u32.u64 %0, t; }" : "=r"(a) : "l"(p));
    return a;
}
#define CP16(dst, src) asm volatile("cp.async.cg.shared.global [%0], [%1], 16;" :: "r"(dst), "l"(src) : "memory")
#define CPCOMMIT()     asm volatile("cp.async.commit_group;" ::: "memory")
#define CPWAIT(n)      asm volatile("cp.async.wait_group %0;" :: "n"(n) : "memory")

__device__ __forceinline__ void ldsm4(uint32_t* r, uint32_t a) {
    asm volatile("ldmatrix.sync.aligned.m8n8.x4.shared.b16 {%0,%1,%2,%3}, [%4];"
        : "=r"(r[0]), "=r"(r[1]), "=r"(r[2]), "=r"(r[3]) : "r"(a));
}
__device__ __forceinline__ void ldsm4t(uint32_t* r, uint32_t a) {
    asm volatile("ldmatrix.sync.aligned.m8n8.x4.trans.shared.b16 {%0,%1,%2,%3}, [%4];"
        : "=r"(r[0]), "=r"(r[1]), "=r"(r[2]), "=r"(r[3]) : "r"(a));
}
__device__ __forceinline__ void mma16(float* c, const uint32_t* a, const uint32_t* b) {
    asm volatile("mma.sync.aligned.m16n8k16.row.col.f32.f16.f16.f32 "
        "{%0,%1,%2,%3}, {%4,%5,%6,%7}, {%8,%9}, {%0,%1,%2,%3};"
        : "+f"(c[0]), "+f"(c[1]), "+f"(c[2]), "+f"(c[3])
        : "r"(a[0]), "r"(a[1]), "r"(a[2]), "r"(a[3]), "r"(b[0]), "r"(b[1]));
}

// ================= stage 1: per-pixel features -> fp16 (2 px/thread, half2 stores) ==========
__global__ __launch_bounds__(256) void kan_feat(const float* __restrict__ x) {
    int i = (blockIdx.x * blockDim.x + threadIdx.x) * 2;
    if (i >= NPIX_TOT) return;
    float2 vv = *(const float2*)(x + i);
    __half2 outp[9];
#pragma unroll
    for (int p = 0; p < 2; ++p) {
        float v = p ? vv.y : vv.x;
        float s = v / (1.0f + expf(-v));
        float un = (v + 2.2f) * 2.5f;
        float sf = floorf(un);
        int   si = (int)sf;
        float u  = un - sf;
        float u2 = u * u, u3 = u2 * u;
        const float c6 = 1.0f / 6.0f;
        float pc[4];
        pc[0] = u3 * c6;
        pc[1] = (1.0f + 3.0f*u + 3.0f*u2 - 3.0f*u3) * c6;
        pc[2] = (4.0f - 6.0f*u2 + 3.0f*u3) * c6;
        pc[3] = (1.0f - 3.0f*u + 3.0f*u2 - u3) * c6;
        bool inr = (si >= 0) && (si <= 10);
        ((__half*)&outp[0])[p] = __float2half_rn(s);
#pragma unroll
        for (int f = 0; f < 8; ++f) {
            int r = si - f;
            float b = (inr && r >= 0 && r <= 3) ? pc[r] : 0.0f;
            ((__half*)&outp[1 + f])[p] = __float2half_rn(b);
        }
    }
#pragma unroll
    for (int f = 0; f < 9; ++f)
        *(__half2*)(g_Fh + f * NPIX_TOT + i) = outp[f];
}

// ================= stage 2: fold weights (fp16) + k-map =================
__global__ __launch_bounds__(256) void kan_wprep(const float* __restrict__ bw,
                                                 const float* __restrict__ sw,
                                                 const float* __restrict__ sc) {
    int idx = blockIdx.x * blockDim.x + threadIdx.x;
    if (idx < KTOT) {
        int c   = idx / 81;
        int rem = idx - c * 81;
        int kk  = rem / 9;
        int f   = rem - kk * 9;
        int ky  = kk / 3;
        int kx  = kk - ky * 3;
        g_kmap[idx] = f * NPIX_TOT + c * (HIN * HIN) + ky * HIN + kx;
    }
    if (idx >= COUT_ * IN_FEAT) return;
    int o = idx & (COUT_ - 1);
    int i = idx >> 7;                        // 0..575 (= c*9+kk)
    float scale = sc[o * IN_FEAT + i];
    __half* dst = g_W2h + o * KTOT + i * 9;
    dst[0] = __float2half_rn(bw[o * IN_FEAT + i]);
#pragma unroll
    for (int g = 0; g < 8; ++g)
        dst[1 + g] = __float2half_rn(sw[(o * IN_FEAT + i) * 8 + g] * scale);
}

// ================= stage 3: fp16 mma.sync GEMM with ldmatrix =================
// CTA 96x128, K in 64-chunks, 3-buffer ring.
// Overlap structure: LDG gather for s+2 issued BEFORE the stage barrier;
// STS + B cp.async interleaved between mma k-groups.
__global__ __launch_bounds__(256, 2) void kan_mma(float* __restrict__ out) {
    extern __shared__ char dsm_raw[];
    __shared__ int sh_ooff[MTILE];

    const uint32_t sb0 = smem_u32(dsm_raw);
    const uint32_t smb = (sb0 + 255) & ~255u;
    char* const dsm = dsm_raw + (smb - sb0);

    const int tid  = threadIdx.x;
    const int wid  = tid >> 5;
    const int lane = tid & 31;

    // ---- producer constants ----
    const int m0 = tid & 7;          // row in 8-group
    const int k1 = tid >> 3;         // 0..31 (second k = k1+32)
    const int base_n = blockIdx.x * MTILE;
    int ro[12];
#pragma unroll
    for (int i = 0; i < 12; ++i) {
        int n   = base_n + m0 + 8 * i;
        int b   = n / PIX_B;
        int rem = n - b * PIX_B;
        int y   = rem / HOUT;
        int xx  = rem - y * HOUT;
        ro[i] = b * (CIN_ * HIN * HIN) + y * HIN + xx;
    }
    if (tid < MTILE) {
        int n   = base_n + tid;
        int b   = n / PIX_B;
        int rem = n - b * PIX_B;
        sh_ooff[tid] = b * (COUT_ * PIX_B) + rem;
    }

    // ---- compute constants ----
    const int wm = wid & 1;          // rows wm*48
    const int wn = wid >> 1;         // cols wn*32
    const uint32_t a_lane = (uint32_t)(((lane & 7) + ((lane >> 4) << 3)) * SAH
                                       + (((lane >> 3) & 1) << 3)) * 2;
    const uint32_t b_lane = (uint32_t)(((lane & 7) + ((lane >> 4) << 3)) * SBH
                                       + (((lane >> 3) & 1) << 3)) * 2;

    float acc[3][4][4];
#pragma unroll
    for (int mt = 0; mt < 3; ++mt)
#pragma unroll
        for (int nt = 0; nt < 4; ++nt)
#pragma unroll
            for (int e = 0; e < 4; ++e) acc[mt][nt][e] = 0.0f;

    __half av[24];

    auto loadA_regs = [&](int s) {
        const int kma = __ldg(g_kmap + s * KC + k1);
        const int kmb = __ldg(g_kmap + s * KC + k1 + 32);
#pragma unroll
        for (int j = 0; j < 12; ++j) {
            av[j]      = g_Fh[kma + ro[j]];
            av[12 + j] = g_Fh[kmb + ro[j]];
        }
    };
    auto stsA = [&](int buf) {
        __half* Ah = (__half*)(dsm + buf * STAGE_BYTES);
#pragma unroll
        for (int j = 0; j < 12; ++j) {
            Ah[k1 * SAH + m0 + 8 * j]        = av[j];
            Ah[(k1 + 32) * SAH + m0 + 8 * j] = av[12 + j];
        }
    };
    auto loadB = [&](int s, int buf) {
        const int n = tid >> 1;
        const __half* src = g_W2h + n * KTOT + s * KC + (tid & 1) * 32;
        uint32_t d = smb + buf * STAGE_BYTES + A_STAGE_BYTES
                   + (uint32_t)(n * SBH + (tid & 1) * 32) * 2;
#pragma unroll
        for (int i = 0; i < 4; ++i)
            CP16(d + i * 16, src + i * 8);
    };

    // ---- prologue: stages 0,1 ----
    loadA_regs(0); stsA(0); loadB(0, 0); CPCOMMIT();
    loadA_regs(1); stsA(1); loadB(1, 1); CPCOMMIT();

    // ---- mainloop ----
    for (int s = 0; s < NSTG; ++s) {
        const int buf = s % NBUF;
        const bool pf = (s + 2 < NSTG);
        const int nb = (s + 2) % NBUF;

        if (pf) loadA_regs(s + 2);       // LDG issued before the barrier: ~full stage of slack

        CPWAIT(1);
        __syncthreads();

        const uint32_t Ab = smb + buf * STAGE_BYTES;
        const uint32_t Bb = Ab + A_STAGE_BYTES;
#pragma unroll
        for (int ks = 0; ks < 4; ++ks) {
            const int k0 = ks * 16;
            uint32_t a[3][4], b[2][4];
#pragma unroll
            for (int mt = 0; mt < 3; ++mt)
                ldsm4t(a[mt], Ab + a_lane
                       + (uint32_t)(k0 * SAH + wm * 48 + mt * 16) * 2);
#pragma unroll
            for (int p = 0; p < 2; ++p)
                ldsm4(b[p], Bb + b_lane
                      + (uint32_t)((wn * 32 + p * 16) * SBH + k0) * 2);

            if (ks == 2 && pf) stsA(nb);        // spread producer STS between mma bursts
            if (ks == 3 && pf) loadB(s + 2, nb);

#pragma unroll
            for (int mt = 0; mt < 3; ++mt)
#pragma unroll
                for (int nt = 0; nt < 4; ++nt)
                    mma16(acc[mt][nt], a[mt], &b[nt >> 1][(nt & 1) * 2]);
        }
        CPCOMMIT();
    }

    CPWAIT(0);
    __syncthreads();

    // ---- epilogue: regs -> smem transpose -> coalesced strided stores ----
    float* sout = (float*)dsm;                 // 96 x SO floats
    const int g  = lane >> 2;
    const int t2 = (lane & 3) * 2;
#pragma unroll
    for (int mt = 0; mt < 3; ++mt) {
        int r = wm * 48 + mt * 16 + g;
#pragma unroll
        for (int nt = 0; nt < 4; ++nt) {
            int cc = wn * 32 + nt * 8 + t2;
            sout[r * SO + cc]           = acc[mt][nt][0];
            sout[r * SO + cc + 1]       = acc[mt][nt][1];
            sout[(r + 8) * SO + cc]     = acc[mt][nt][2];
            sout[(r + 8) * SO + cc + 1] = acc[mt][nt][3];
        }
    }
    __syncthreads();
#pragma unroll
    for (int o = wid; o < COUT_; o += 8) {
#pragma unroll
        for (int rg = 0; rg < 3; ++rg) {
            int r = rg * 32 + lane;
            out[sh_ooff[r] + o * PIX_B] = sout[r * SO + o];
        }
    }
}

// ================= launch =================
extern "C" void kernel_launch(void* const* d_in, const int* in_sizes, int n_in,
                              void* d_out, int out_size) {
    const float* x  = (const float*)d_in[0];   // (8,64,56,56)
    const float* bw = (const float*)d_in[1];   // (128,576)
    const float* sw = (const float*)d_in[2];   // (128,576,8)
    const float* sc = (const float*)d_in[3];   // (128,576)
    float* out = (float*)d_out;                // (8,128,54,54)
    (void)in_sizes; (void)n_in; (void)out_size;

    cudaFuncSetAttribute(kan_mma, cudaFuncAttributeMaxDynamicSharedMemorySize, DYN_SMEM);

    kan_feat<<<(NPIX_TOT / 2 + 255) / 256, 256>>>(x);
    kan_wprep<<<(COUT_ * IN_FEAT + 255) / 256, 256>>>(bw, sw, sc);
    kan_mma<<<CTAS, 256, DYN_SMEM>>>(out);
}

// round 7
// speedup vs baseline: 6.5326x; 1.3839x over previous
#include <cuda_runtime.h>
#include <cuda_fp16.h>
#include <cstdint>
#include <math.h>

// ================= problem constants =================
#define CIN_     64
#define HIN      56
#define HOUT     54
#define PIX_B    (HOUT * HOUT)              // 2916
#define BATCH    8
#define NPIX_TOT (BATCH * CIN_ * HIN * HIN) // 1605632
#define NROWS    (BATCH * PIX_B)            // 23328
#define COUT_    128
#define KSPL     4608                        // spline K: 576 (c,kk) * 8 f
#define KTOT     5184                        // + 576 silu
#define KC       64                          // K per stage
#define NSTG     (KTOT / KC)                 // 81 (72 spline + 9 silu)
#define NSPL_STG 72
#define MTILE    96
#define CTAS     (NROWS / MTILE)             // 243 exact

// smem geometry (halves)
#define SAK      72                          // A [m][k] row stride (9*16B, conflict-free)
#define SBH      72                          // B [n][k] row stride
#define A_STAGE_BYTES (MTILE * SAK * 2)      // 13824
#define B_STAGE_BYTES (COUT_ * SBH * 2)      // 18432
#define STAGE_BYTES   (A_STAGE_BYTES + B_STAGE_BYTES)  // 32256
#define NBUF     3
#define DYN_SMEM (NBUF * STAGE_BYTES + 256)  // 97024
#define SO       132                         // epilogue sout stride (floats)

// ================= device scratch (static; no allocs) =================
__device__ uint4  g_Fs[NPIX_TOT];            // 8 packed spline halves per pixel (16B)
__device__ __half g_Fsilu[NPIX_TOT];         // silu plane
__device__ __half g_W2h[COUT_ * KTOT];       // weights [o][k]: k<4608 spline (c,kk,f), then silu
__device__ int    g_kmap2[576];              // (c*9+kk) -> c*3136 + ky*56 + kx

// ================= helpers =================
__device__ __forceinline__ uint32_t smem_u32(const void* p) {
    uint32_t a;
    asm("{ .reg .u64 t; cvta.to.shared.u64 t, %1; cvt.u32.u64 %0, t; }" : "=r"(a) : "l"(p));
    return a;
}
#define CP16(dst, src) asm volatile("cp.async.cg.shared.global [%0], [%1], 16;" :: "r"(dst), "l"(src) : "memory")
#define CPCOMMIT()     asm volatile("cp.async.commit_group;" ::: "memory")
#define CPWAIT(n)      asm volatile("cp.async.wait_group %0;" :: "n"(n) : "memory")

__device__ __forceinline__ void ldsm4(uint32_t* r, uint32_t a) {
    asm volatile("ldmatrix.sync.aligned.m8n8.x4.shared.b16 {%0,%1,%2,%3}, [%4];"
        : "=r"(r[0]), "=r"(r[1]), "=r"(r[2]), "=r"(r[3]) : "r"(a));
}
__device__ __forceinline__ void mma16(float* c, const uint32_t* a, const uint32_t* b) {
    asm volatile("mma.sync.aligned.m16n8k16.row.col.f32.f16.f16.f32 "
        "{%0,%1,%2,%3}, {%4,%5,%6,%7}, {%8,%9}, {%0,%1,%2,%3};"
        : "+f"(c[0]), "+f"(c[1]), "+f"(c[2]), "+f"(c[3])
        : "r"(a[0]), "r"(a[1]), "r"(a[2]), "r"(a[3]), "r"(b[0]), "r"(b[1]));
}

// ================= stage 1: per-pixel features =================
__global__ __launch_bounds__(256) void kan_feat(const float* __restrict__ x) {
    int i = (blockIdx.x * blockDim.x + threadIdx.x) * 2;
    if (i >= NPIX_TOT) return;
    float2 vv = *(const float2*)(x + i);
    __half2 sil;
    uint4 spl[2];
#pragma unroll
    for (int p = 0; p < 2; ++p) {
        float v = p ? vv.y : vv.x;
        float s = v / (1.0f + expf(-v));
        float un = (v + 2.2f) * 2.5f;
        float sf = floorf(un);
        int   si = (int)sf;
        float u  = un - sf;
        float u2 = u * u, u3 = u2 * u;
        const float c6 = 1.0f / 6.0f;
        float pc[4];
        pc[0] = u3 * c6;
        pc[1] = (1.0f + 3.0f*u + 3.0f*u2 - 3.0f*u3) * c6;
        pc[2] = (4.0f - 6.0f*u2 + 3.0f*u3) * c6;
        pc[3] = (1.0f - 3.0f*u + 3.0f*u2 - u3) * c6;
        bool inr = (si >= 0) && (si <= 10);
        ((__half*)&sil)[p] = __float2half_rn(s);
        __half* sp = (__half*)&spl[p];
#pragma unroll
        for (int f = 0; f < 8; ++f) {
            int r = si - f;
            float b = (inr && r >= 0 && r <= 3) ? pc[r] : 0.0f;
            sp[f] = __float2half_rn(b);
        }
    }
    *(__half2*)(g_Fsilu + i) = sil;
    g_Fs[i]     = spl[0];
    g_Fs[i + 1] = spl[1];
}

// ================= stage 2: weights + tap map =================
__global__ __launch_bounds__(256) void kan_wprep(const float* __restrict__ bw,
                                                 const float* __restrict__ sw,
                                                 const float* __restrict__ sc) {
    int idx = blockIdx.x * blockDim.x + threadIdx.x;
    if (idx < 576) {
        int c  = idx / 9;
        int kk = idx - c * 9;
        int ky = kk / 3;
        int kx = kk - ky * 3;
        g_kmap2[idx] = c * (HIN * HIN) + ky * HIN + kx;
    }
    if (idx >= COUT_ * 576) return;
    int o = idx & (COUT_ - 1);
    int i = idx >> 7;                        // 0..575 (= c*9+kk)
    float scale = sc[o * 576 + i];
    __half* dst = g_W2h + o * KTOT + i * 8;  // spline block: k = i*8 + f
#pragma unroll
    for (int g = 0; g < 8; ++g)
        dst[g] = __float2half_rn(sw[(o * 576 + i) * 8 + g] * scale);
    g_W2h[o * KTOT + KSPL + i] = __float2half_rn(bw[o * 576 + i]);   // silu block
}

// ================= stage 3: fp16 mma.sync GEMM =================
// CTA 96x128. A [m][k] row-major smem (stride 72), B [n][k] (stride 72), 3-buf ring.
// Spline stages: vector gather (LDG.128 of 8 packed f -> STS.128).
// Silu stages (last 9): scalar gather.
__global__ __launch_bounds__(256, 2) void kan_mma(float* __restrict__ out) {
    extern __shared__ char dsm_raw[];
    __shared__ int sh_roff[MTILE];
    __shared__ int sh_ooff[MTILE];

    const uint32_t sb0 = smem_u32(dsm_raw);
    const uint32_t smb = (sb0 + 255) & ~255u;
    char* const dsm = dsm_raw + (smb - sb0);

    const int tid  = threadIdx.x;
    const int wid  = tid >> 5;
    const int lane = tid & 31;
    const int base_n = blockIdx.x * MTILE;

    if (tid < MTILE) {
        int n   = base_n + tid;
        int b   = n / PIX_B;
        int rem = n - b * PIX_B;
        int y   = rem / HOUT;
        int xx  = rem - y * HOUT;
        sh_roff[tid] = b * (CIN_ * HIN * HIN) + y * HIN + xx;
        sh_ooff[tid] = b * (COUT_ * PIX_B) + rem;
    }
    __syncthreads();

    // producer constants
    const int gsel = tid >> 5;               // spline: f-group / (c,kk) group 0..7
    const int mv   = tid & 31;               // spline: m = mv + 32j
    const int m0   = tid & 7;                // silu: m = m0 + 8j
    const int k1   = tid >> 3;               // silu: k = k1, k1+32

    // compute constants
    const int wm = wid & 1;
    const int wn = wid >> 1;
    const uint32_t a_lane = (uint32_t)(((lane & 7) + (((lane >> 3) & 1) << 3)) * SAK
                                       + ((lane >> 4) << 3)) * 2;
    const uint32_t b_lane = (uint32_t)(((lane & 7) + ((lane >> 4) << 3)) * SBH
                                       + (((lane >> 3) & 1) << 3)) * 2;

    float acc[3][4][4];
#pragma unroll
    for (int mt = 0; mt < 3; ++mt)
#pragma unroll
        for (int nt = 0; nt < 4; ++nt)
#pragma unroll
            for (int e = 0; e < 4; ++e) acc[mt][nt][e] = 0.0f;

    uint4  va[3];     // spline prefetch
    __half av[24];    // silu prefetch

    auto loadA = [&](int s) {
        if (s < NSPL_STG) {
            const int km = __ldg(g_kmap2 + s * 8 + gsel);
#pragma unroll
            for (int j = 0; j < 3; ++j)
                va[j] = __ldg(g_Fs + km + sh_roff[mv + 32 * j]);
        } else {
            const int c0 = (s - NSPL_STG) * 64 + k1;
            const int km0 = __ldg(g_kmap2 + c0);
            const int km1 = __ldg(g_kmap2 + c0 + 32);
#pragma unroll
            for (int j = 0; j < 12; ++j) {
                int ro = sh_roff[m0 + 8 * j];
                av[j]      = g_Fsilu[km0 + ro];
                av[12 + j] = g_Fsilu[km1 + ro];
            }
        }
    };
    auto stsA = [&](int s, int buf) {
        __half* Ah = (__half*)(dsm + buf * STAGE_BYTES);
        if (s < NSPL_STG) {
#pragma unroll
            for (int j = 0; j < 3; ++j)
                *(uint4*)(Ah + (mv + 32 * j) * SAK + gsel * 8) = va[j];
        } else {
#pragma unroll
            for (int j = 0; j < 12; ++j) {
                Ah[(m0 + 8 * j) * SAK + k1]      = av[j];
                Ah[(m0 + 8 * j) * SAK + k1 + 32] = av[12 + j];
            }
        }
    };
    auto loadB = [&](int s, int buf) {
        const int n = tid >> 1;
        const __half* src = g_W2h + n * KTOT + s * KC + (tid & 1) * 32;
        uint32_t d = smb + buf * STAGE_BYTES + A_STAGE_BYTES
                   + (uint32_t)(n * SBH + (tid & 1) * 32) * 2;
#pragma unroll
        for (int i = 0; i < 4; ++i)
            CP16(d + i * 16, src + i * 8);
    };

    // prologue
    loadA(0); stsA(0, 0); loadB(0, 0); CPCOMMIT();
    loadA(1); stsA(1, 1); loadB(1, 1); CPCOMMIT();

    // mainloop
    for (int s = 0; s < NSTG; ++s) {
        const int buf = s % NBUF;
        const bool pf = (s + 2 < NSTG);
        const int nb = (s + 2) % NBUF;

        if (pf) loadA(s + 2);                 // gmem LDG before the barrier

        CPWAIT(1);
        __syncthreads();

        const uint32_t Ab = smb + buf * STAGE_BYTES;
        const uint32_t Bb = Ab + A_STAGE_BYTES;
#pragma unroll
        for (int ks = 0; ks < 4; ++ks) {
            const int k0 = ks * 16;
            uint32_t a[3][4], b[2][4];
#pragma unroll
            for (int mt = 0; mt < 3; ++mt)
                ldsm4(a[mt], Ab + a_lane
                      + (uint32_t)((wm * 48 + mt * 16) * SAK + k0) * 2);
#pragma unroll
            for (int p = 0; p < 2; ++p)
                ldsm4(b[p], Bb + b_lane
                      + (uint32_t)((wn * 32 + p * 16) * SBH + k0) * 2);

            if (ks == 2 && pf) stsA(s + 2, nb);
            if (ks == 3 && pf) loadB(s + 2, nb);

#pragma unroll
            for (int mt = 0; mt < 3; ++mt)
#pragma unroll
                for (int nt = 0; nt < 4; ++nt)
                    mma16(acc[mt][nt], a[mt], &b[nt >> 1][(nt & 1) * 2]);
        }
        CPCOMMIT();
    }

    CPWAIT(0);
    __syncthreads();

    // epilogue: regs -> smem transpose -> coalesced strided stores
    float* sout = (float*)dsm;
    const int g  = lane >> 2;
    const int t2 = (lane & 3) * 2;
#pragma unroll
    for (int mt = 0; mt < 3; ++mt) {
        int r = wm * 48 + mt * 16 + g;
#pragma unroll
        for (int nt = 0; nt < 4; ++nt) {
            int cc = wn * 32 + nt * 8 + t2;
            sout[r * SO + cc]           = acc[mt][nt][0];
            sout[r * SO + cc + 1]       = acc[mt][nt][1];
            sout[(r + 8) * SO + cc]     = acc[mt][nt][2];
            sout[(r + 8) * SO + cc + 1] = acc[mt][nt][3];
        }
    }
    __syncthreads();
#pragma unroll
    for (int o = wid; o < COUT_; o += 8) {
#pragma unroll
        for (int rg = 0; rg < 3; ++rg) {
            int r = rg * 32 + lane;
            out[sh_ooff[r] + o * PIX_B] = sout[r * SO + o];
        }
    }
}

// ================= launch =================
extern "C" void kernel_launch(void* const* d_in, const int* in_sizes, int n_in,
                              void* d_out, int out_size) {
    const float* x  = (const float*)d_in[0];   // (8,64,56,56)
    const float* bw = (const float*)d_in[1];   // (128,576)
    const float* sw = (const float*)d_in[2];   // (128,576,8)
    const float* sc = (const float*)d_in[3];   // (128,576)
    float* out = (float*)d_out;                // (8,128,54,54)
    (void)in_sizes; (void)n_in; (void)out_size;

    cudaFuncSetAttribute(kan_mma, cudaFuncAttributeMaxDynamicSharedMemorySize, DYN_SMEM);

    kan_feat<<<(NPIX_TOT / 2 + 255) / 256, 256>>>(x);
    kan_wprep<<<(COUT_ * 576 + 255) / 256, 256>>>(bw, sw, sc);
    kan_mma<<<CTAS, 256, DYN_SMEM>>>(out);
}